// round 13
// baseline (speedup 1.0000x reference)
#include <cuda_runtime.h>
#include <math.h>
#include <stdint.h>

// ---------------------------------------------------------------------------
// Problem constants
// ---------------------------------------------------------------------------
#define NN     50000
#define EE     400000
#define F_IN   128
#define H0     4
#define C0     64
#define F0     (H0*C0)    // 256
#define H1     1
#define C1     256
#define F1     256
#define NCLS   10
#define SLOPE  0.2f

// ---------------------------------------------------------------------------
// Scratch (device globals)
// ---------------------------------------------------------------------------
__device__ float g_h   [NN * 256];      // GEMM1/2 fp32 output (alpha + gather)
__device__ float g_t2  [NN * 1024];     // GEMM4 fp32 output (final)
__device__ float g_asrc[NN * H0];
__device__ float g_adst[NN * H0];
// packed bf16x2 hi/lo activations (word = k-pair)
__device__ uint32_t g_xh [NN * 64],  g_xl [NN * 64];    // x    K=128
__device__ uint32_t g_o1h[NN * 128], g_o1l[NN * 128];   // out0 K=256
__device__ uint32_t g_o2h[NN * 128], g_o2l[NN * 128];   // out1 K=256
__device__ uint32_t g_t1h[NN * 256], g_t1l[NN * 256];   // t1   K=512
// packed bf16x2 hi/lo transposed weights [N, K/2]
__device__ uint32_t g_w0h[256 * 64],   g_w0l[256 * 64];
__device__ uint32_t g_w1h[256 * 128],  g_w1l[256 * 128];
__device__ uint32_t g_w2h[512 * 128],  g_w2l[512 * 128];
__device__ uint32_t g_w3h[1024 * 256], g_w3l[1024 * 256];
// CSR by destination
__device__ int g_cnt [NN];
__device__ int g_offs[NN + 1];
__device__ int g_cur [NN];
__device__ int g_csrc[EE];

// ---------------------------------------------------------------------------
// helpers (baseline PTX: sm_80-era mma.sync bf16 + cp.async + ldmatrix)
// ---------------------------------------------------------------------------
__device__ __forceinline__ uint32_t pack_bf16(float hi, float lo) {
    uint32_t r;
    asm("cvt.rn.bf16x2.f32 %0, %1, %2;" : "=r"(r) : "f"(hi), "f"(lo));
    return r;
}

// split float2 (p.x = k even, p.y = k odd) into bf16x2 hi + bf16x2 residual
__device__ __forceinline__ void split2(float2 p, uint32_t& h, uint32_t& l) {
    h = pack_bf16(p.y, p.x);
    float rhi = p.y - __uint_as_float(h & 0xFFFF0000u);
    float rlo = p.x - __uint_as_float(h << 16);
    l = pack_bf16(rhi, rlo);
}

__device__ __forceinline__ void mma16(float c[4], const uint32_t a[4],
                                      uint32_t b0, uint32_t b1) {
    asm volatile(
        "mma.sync.aligned.m16n8k16.row.col.f32.bf16.bf16.f32 "
        "{%0,%1,%2,%3}, {%4,%5,%6,%7}, {%8,%9}, {%0,%1,%2,%3};"
        : "+f"(c[0]), "+f"(c[1]), "+f"(c[2]), "+f"(c[3])
        : "r"(a[0]), "r"(a[1]), "r"(a[2]), "r"(a[3]), "r"(b0), "r"(b1));
}

__device__ __forceinline__ void ldsm_x4(uint32_t& r0, uint32_t& r1,
                                        uint32_t& r2, uint32_t& r3,
                                        uint32_t addr) {
    asm volatile("ldmatrix.sync.aligned.m8n8.x4.shared.b16 {%0,%1,%2,%3}, [%4];"
                 : "=r"(r0), "=r"(r1), "=r"(r2), "=r"(r3) : "r"(addr));
}

__device__ __forceinline__ uint32_t smem_u32(const void* p) {
    uint32_t a;
    asm("{ .reg .u64 t; cvta.to.shared.u64 t, %1; cvt.u32.u64 %0, t; }"
        : "=r"(a) : "l"(p));
    return a;
}

__device__ __forceinline__ void cp16(uint32_t dst, const void* src, int srcsize) {
    asm volatile("cp.async.ca.shared.global [%0], [%1], 16, %2;"
                 :: "r"(dst), "l"(src), "r"(srcsize));
}
#define CP_COMMIT() asm volatile("cp.async.commit_group;")
#define CP_WAIT(n)  asm volatile("cp.async.wait_group %0;" :: "n"(n))

// ---------------------------------------------------------------------------
// BF16x3 tensor-core GEMM, FULLY-PACKED operands.
// Both A and B arrive pre-split as packed bf16x2 hi/lo [rows, K/2].
// C[M,N] = A[M,K] @ Bt[N,K]^T  (+bias, +relu; fp32 C and/or packed C out)
// CTA 128x128, BK=32 (16 words), 256 threads (8 warps 2x4), warp 64x32.
// Double-buffered; ONE __syncthreads per chunk; mainloop = ldmatrix.x4 + HMMA.
// products: ah*bh + ah*bl + al*bh (fp32 accum, rel err ~1e-6).
// Packed pitch 20 words (80B) -> ldmatrix 8-row phases cover all 32 banks.
// N % 128 == 0, K % 32 == 0; M guarded.
// ---------------------------------------------------------------------------
#define PADP 20
#define PK_W (128 * PADP)                  // 2560 words per array
#define STG_STRIDE (4 * PK_W)              // words per stage {Ah,Al,Bh,Bl}
#define GEMM_SMEM_BYTES (2 * STG_STRIDE * 4)   // 81920 B

__global__ __launch_bounds__(256, 2)
void mma_gemm(int M, int N, int K,
              const uint32_t* __restrict__ Ah_g, const uint32_t* __restrict__ Al_g,
              const uint32_t* __restrict__ Bh_g, const uint32_t* __restrict__ Bl_g,
              const float* __restrict__ bias, float* __restrict__ C, int do_relu,
              uint32_t* __restrict__ Ch_g, uint32_t* __restrict__ Cl_g)
{
    extern __shared__ uint32_t smw[];
    const uint32_t smbase = smem_u32(smw);

    const int tid  = threadIdx.x;
    const int wid  = tid >> 5;
    const int lane = tid & 31;
    const int g    = lane >> 2;
    const int tig  = lane & 3;
    const int warpRow = (wid & 1) * 64;
    const int warpCol = (wid >> 1) * 32;
    const int rowBase = blockIdx.y * 128;
    const int colBase = blockIdx.x * 128;
    const int Kw = K >> 1;

    float acc[4][4][4];
    #pragma unroll
    for (int mf = 0; mf < 4; mf++)
        #pragma unroll
        for (int nf = 0; nf < 4; nf++)
            #pragma unroll
            for (int r = 0; r < 4; r++) acc[mf][nf][r] = 0.0f;

    // loader: thread -> (operand, row); 8 cp16/thread/chunk (hi+lo, 16 words each)
    const int lrow = tid & 127;
    const int isB  = tid >> 7;
    const uint32_t* gh = isB ? Bh_g + (size_t)(colBase + lrow) * Kw
                             : Ah_g + (size_t)(rowBase + lrow) * Kw;
    const uint32_t* gl = isB ? Bl_g + (size_t)(colBase + lrow) * Kw
                             : Al_g + (size_t)(rowBase + lrow) * Kw;
    const int srcsz = (!isB && (rowBase + lrow) >= M) ? 0 : 16;
    const uint32_t dstw = (uint32_t)(isB ? 2 * PK_W : 0) + lrow * PADP;

    const int nch = K / 32;

    // prologue: stage 0, chunk 0
    {
        uint32_t dh = smbase + (dstw << 2);
        uint32_t dl = dh + (PK_W << 2);
        cp16(dh,      gh,     srcsz); cp16(dh + 16, gh + 4,  srcsz);
        cp16(dh + 32, gh + 8, srcsz); cp16(dh + 48, gh + 12, srcsz);
        cp16(dl,      gl,     srcsz); cp16(dl + 16, gl + 4,  srcsz);
        cp16(dl + 32, gl + 8, srcsz); cp16(dl + 48, gl + 12, srcsz);
        CP_COMMIT();
    }

    // ldmatrix base addresses (stage offset added in the loop)
    const uint32_t aAddr = smbase
        + (uint32_t)(warpRow + (lane & 15)) * PADP * 4 + (uint32_t)(lane >> 4) * 16;
    const uint32_t bAddr = smbase + (uint32_t)(2 * PK_W) * 4
        + (uint32_t)(warpCol + ((lane >> 4) * 8) + (lane & 7)) * PADP * 4
        + (uint32_t)((lane >> 3) & 1) * 16;

    for (int kc = 0; kc < nch; kc++) {
        CP_WAIT(0);
        __syncthreads();    // stage kc ready; previous compute done

        // prefetch chunk kc+1 into the other stage (overlaps compute below)
        if (kc + 1 < nch) {
            const uint32_t so = (uint32_t)((kc + 1) & 1) * STG_STRIDE;
            const int kw = (kc + 1) * 16;
            uint32_t dh = smbase + ((so + dstw) << 2);
            uint32_t dl = dh + (PK_W << 2);
            cp16(dh,      gh + kw,      srcsz); cp16(dh + 16, gh + kw + 4,  srcsz);
            cp16(dh + 32, gh + kw + 8,  srcsz); cp16(dh + 48, gh + kw + 12, srcsz);
            cp16(dl,      gl + kw,      srcsz); cp16(dl + 16, gl + kw + 4,  srcsz);
            cp16(dl + 32, gl + kw + 8,  srcsz); cp16(dl + 48, gl + kw + 12, srcsz);
            CP_COMMIT();
        }

        const uint32_t stOff = (uint32_t)(kc & 1) * STG_STRIDE * 4;

        #pragma unroll
        for (int ks = 0; ks < 2; ks++) {
            const uint32_t ko = stOff + (uint32_t)ks * 32;   // 8 words = 32B
            uint32_t ah[4][4], al[4][4];
            #pragma unroll
            for (int mf = 0; mf < 4; mf++) {
                uint32_t a = aAddr + (uint32_t)mf * (16 * PADP * 4) + ko;
                ldsm_x4(ah[mf][0], ah[mf][1], ah[mf][2], ah[mf][3], a);
                ldsm_x4(al[mf][0], al[mf][1], al[mf][2], al[mf][3], a + PK_W * 4);
            }
            #pragma unroll
            for (int p = 0; p < 2; p++) {
                uint32_t b = bAddr + (uint32_t)p * (16 * PADP * 4) + ko;
                uint32_t bh0a, bh1a, bh0b, bh1b;
                uint32_t bl0a, bl1a, bl0b, bl1b;
                ldsm_x4(bh0a, bh1a, bh0b, bh1b, b);
                ldsm_x4(bl0a, bl1a, bl0b, bl1b, b + PK_W * 4);
                const int nf0 = 2 * p, nf1 = 2 * p + 1;
                #pragma unroll
                for (int mf = 0; mf < 4; mf++) {
                    mma16(acc[mf][nf0], ah[mf], bh0a, bh1a);
                    mma16(acc[mf][nf0], ah[mf], bl0a, bl1a);
                    mma16(acc[mf][nf0], al[mf], bh0a, bh1a);
                    mma16(acc[mf][nf1], ah[mf], bh0b, bh1b);
                    mma16(acc[mf][nf1], ah[mf], bl0b, bl1b);
                    mma16(acc[mf][nf1], al[mf], bh0b, bh1b);
                }
            }
        }
    }

    // ---- epilogue ----
    const int Nw = N >> 1;
    #pragma unroll
    for (int mf = 0; mf < 4; mf++) {
        int r0 = rowBase + warpRow + mf * 16 + g;
        int r1 = r0 + 8;
        #pragma unroll
        for (int nf = 0; nf < 4; nf++) {
            int col = colBase + warpCol + nf * 8 + tig * 2;
            float b0v = 0.f, b1v = 0.f;
            if (bias) { b0v = bias[col]; b1v = bias[col + 1]; }
            float2 v0 = make_float2(acc[mf][nf][0] + b0v, acc[mf][nf][1] + b1v);
            float2 v1 = make_float2(acc[mf][nf][2] + b0v, acc[mf][nf][3] + b1v);
            if (do_relu) {
                v0.x = fmaxf(v0.x, 0.f); v0.y = fmaxf(v0.y, 0.f);
                v1.x = fmaxf(v1.x, 0.f); v1.y = fmaxf(v1.y, 0.f);
            }
            if (r0 < M) {
                if (C) *(float2*)&C[(size_t)r0 * N + col] = v0;
                if (Ch_g) {
                    uint32_t h, l; split2(v0, h, l);
                    size_t w = (size_t)r0 * Nw + (col >> 1);
                    Ch_g[w] = h; Cl_g[w] = l;
                }
            }
            if (r1 < M) {
                if (C) *(float2*)&C[(size_t)r1 * N + col] = v1;
                if (Ch_g) {
                    uint32_t h, l; split2(v1, h, l);
                    size_t w = (size_t)r1 * Nw + (col >> 1);
                    Ch_g[w] = h; Cl_g[w] = l;
                }
            }
        }
    }
}

// ---------------------------------------------------------------------------
// Weight transpose + bf16 split: W[K,N] -> packed hi/lo [N, K/2]
// ---------------------------------------------------------------------------
__global__ void transpose_split_kernel(const float* __restrict__ W,
                                       uint32_t* __restrict__ oh,
                                       uint32_t* __restrict__ ol, int K, int N)
{
    __shared__ float t[32][33];
    int kb = blockIdx.y * 32, nb = blockIdx.x * 32;
    int tx = threadIdx.x, ty = threadIdx.y;
    t[ty][tx] = W[(size_t)(kb + ty) * N + nb + tx];
    __syncthreads();
    if (tx < 16) {
        int n2 = nb + ty;
        int kp = (kb >> 1) + tx;
        uint32_t h, l;
        split2(make_float2(t[2 * tx][ty], t[2 * tx + 1][ty]), h, l);
        oh[(size_t)n2 * (K >> 1) + kp] = h;
        ol[(size_t)n2 * (K >> 1) + kp] = l;
    }
}

// ---------------------------------------------------------------------------
// Elementwise split: fp32 -> packed hi/lo (for x)
// ---------------------------------------------------------------------------
__global__ void split_kernel(const float4* __restrict__ x,
                             uint32_t* __restrict__ oh,
                             uint32_t* __restrict__ ol, int total4)
{
    int i = blockIdx.x * blockDim.x + threadIdx.x;
    if (i >= total4) return;
    float4 v = x[i];
    uint32_t h0, l0, h1, l1;
    split2(make_float2(v.x, v.y), h0, l0);
    split2(make_float2(v.z, v.w), h1, l1);
    oh[2 * i] = h0; oh[2 * i + 1] = h1;
    ol[2 * i] = l0; ol[2 * i + 1] = l1;
}

// ---------------------------------------------------------------------------
// CSR build
// ---------------------------------------------------------------------------
__global__ void csr_count_kernel(const int* __restrict__ ei, int E,
                                 int* __restrict__ cnt)
{
    int i = blockIdx.x * blockDim.x + threadIdx.x;
    if (i < E) atomicAdd(&cnt[ei[E + i]], 1);
}

__global__ __launch_bounds__(1024) void csr_scan_kernel(
    const int* __restrict__ cnt, int* __restrict__ offs,
    int* __restrict__ cur, int n)
{
    __shared__ int sm[1024];
    __shared__ int carry;
    if (threadIdx.x == 0) { carry = 0; offs[0] = 0; }
    __syncthreads();
    for (int base = 0; base < n; base += 1024) {
        int i = base + threadIdx.x;
        int v = (i < n) ? cnt[i] : 0;
        sm[threadIdx.x] = v;
        __syncthreads();
        #pragma unroll
        for (int off = 1; off < 1024; off <<= 1) {
            int t = (threadIdx.x >= off) ? sm[threadIdx.x - off] : 0;
            __syncthreads();
            sm[threadIdx.x] += t;
            __syncthreads();
        }
        if (i < n) {
            int inc = carry + sm[threadIdx.x];
            offs[i + 1] = inc;
            cur[i] = inc - v;
        }
        __syncthreads();
        if (threadIdx.x == 0) carry += sm[1023];
        __syncthreads();
    }
}

__global__ void csr_scatter_kernel(const int* __restrict__ ei, int E,
                                   int* __restrict__ cur,
                                   int* __restrict__ csrc)
{
    int i = blockIdx.x * blockDim.x + threadIdx.x;
    if (i >= E) return;
    int d = ei[E + i];
    int p = atomicAdd(&cur[d], 1);
    csrc[p] = ei[i];
}

// ---------------------------------------------------------------------------
// alpha_src/alpha_dst per (node, head)
// ---------------------------------------------------------------------------
__global__ void alpha_init_kernel(
    const float* __restrict__ h, const float* __restrict__ a_src,
    const float* __restrict__ a_dst, int Nn, int H, int C,
    float* __restrict__ asrc, float* __restrict__ adst)
{
    int idx  = (blockIdx.x * blockDim.x + threadIdx.x) >> 5;
    int lane = threadIdx.x & 31;
    if (idx >= Nn * H) return;
    int node = idx / H;
    int head = idx % H;

    const float* hp = h + (size_t)node * H * C + head * C;
    const float* as = a_src + head * C;
    const float* ad = a_dst + head * C;
    float s1 = 0.f, s2 = 0.f;
    for (int c = lane; c < C; c += 32) {
        float v = hp[c];
        s1 = fmaf(v, as[c], s1);
        s2 = fmaf(v, ad[c], s2);
    }
    #pragma unroll
    for (int off = 16; off; off >>= 1) {
        s1 += __shfl_xor_sync(0xffffffffu, s1, off);
        s2 += __shfl_xor_sync(0xffffffffu, s2, off);
    }
    if (lane == 0) {
        asrc[idx] = s1;
        adst[idx] = s2;
    }
}

// ---------------------------------------------------------------------------
// Fused CSR aggregation, PACKED bf16 hi/lo output (feeds next GEMM).
// One warp per destination node; F = 256. No atomics.
// ---------------------------------------------------------------------------
__global__ void aggregate_csr_kernel(
    const int* __restrict__ offs, const int* __restrict__ csrc,
    const float* __restrict__ asrc, const float* __restrict__ adst,
    const float* __restrict__ hfeat, const float* __restrict__ bias,
    int Nn, int H, int cshift,
    uint32_t* __restrict__ outh, uint32_t* __restrict__ outl)
{
    int node = (blockIdx.x * blockDim.x + threadIdx.x) >> 5;
    int lane = threadIdx.x & 31;
    if (node >= Nn) return;
    const int hsel = (H > 1) ? (lane >> (cshift - 3)) : 0;

    const float adn = adst[node * H + hsel];

    float v = asrc[node * H + hsel] + adn;
    float w = expf((v > 0.f) ? v : SLOPE * v);
    float wsum = w;
    const float4* hp = (const float4*)(hfeat + (size_t)node * 256 + lane * 8);
    float4 u = hp[0], vv4 = hp[1];
    float a0 = w * u.x,   a1 = w * u.y,   a2 = w * u.z,   a3 = w * u.w;
    float a4 = w * vv4.x, a5 = w * vv4.y, a6 = w * vv4.z, a7 = w * vv4.w;

    const int e1 = offs[node + 1];
    for (int e = offs[node]; e < e1; e++) {
        int s = csrc[e];
        if (s != node) {
            float ve = asrc[s * H + hsel] + adn;
            float we = expf((ve > 0.f) ? ve : SLOPE * ve);
            wsum += we;
            const float4* sp = (const float4*)(hfeat + (size_t)s * 256 + lane * 8);
            float4 p = sp[0], q = sp[1];
            a0 = fmaf(we, p.x, a0); a1 = fmaf(we, p.y, a1);
            a2 = fmaf(we, p.z, a2); a3 = fmaf(we, p.w, a3);
            a4 = fmaf(we, q.x, a4); a5 = fmaf(we, q.y, a5);
            a6 = fmaf(we, q.z, a6); a7 = fmaf(we, q.w, a7);
        }
    }

    const float inv = 1.0f / wsum;
    const int colb = lane * 8;
    float o0 = fmaxf(fmaf(a0, inv, bias[colb + 0]), 0.f);
    float o1 = fmaxf(fmaf(a1, inv, bias[colb + 1]), 0.f);
    float o2 = fmaxf(fmaf(a2, inv, bias[colb + 2]), 0.f);
    float o3 = fmaxf(fmaf(a3, inv, bias[colb + 3]), 0.f);
    float o4 = fmaxf(fmaf(a4, inv, bias[colb + 4]), 0.f);
    float o5 = fmaxf(fmaf(a5, inv, bias[colb + 5]), 0.f);
    float o6 = fmaxf(fmaf(a6, inv, bias[colb + 6]), 0.f);
    float o7 = fmaxf(fmaf(a7, inv, bias[colb + 7]), 0.f);

    uint32_t h0, l0, h1, l1, h2, l2, h3, l3;
    split2(make_float2(o0, o1), h0, l0);
    split2(make_float2(o2, o3), h1, l1);
    split2(make_float2(o4, o5), h2, l2);
    split2(make_float2(o6, o7), h3, l3);
    size_t wbase = (size_t)node * 128 + lane * 4;
    *(uint4*)&outh[wbase] = make_uint4(h0, h1, h2, h3);
    *(uint4*)&outl[wbase] = make_uint4(l0, l1, l2, l3);
}

// ---------------------------------------------------------------------------
// Final: out = softmax(relu(X @ lw3 + lb3)), X:[N,1024]
// ---------------------------------------------------------------------------
__global__ __launch_bounds__(128) void final_kernel(
    const float* __restrict__ X, const float* __restrict__ W,
    const float* __restrict__ b, float* __restrict__ out, int K)
{
    int n = blockIdx.x;
    const float* x = X + (size_t)n * K;

    float acc[NCLS];
    #pragma unroll
    for (int c = 0; c < NCLS; c++) acc[c] = 0.f;

    for (int k = threadIdx.x; k < K; k += 128) {
        float xv = x[k];
        const float* wr = W + (size_t)k * NCLS;
        #pragma unroll
        for (int c = 0; c < NCLS; c++) acc[c] = fmaf(xv, wr[c], acc[c]);
    }
    #pragma unroll
    for (int c = 0; c < NCLS; c++)
        #pragma unroll
        for (int off = 16; off; off >>= 1)
            acc[c] += __shfl_xor_sync(0xffffffffu, acc[c], off);

    __shared__ float sm[4][NCLS];
    int warp = threadIdx.x >> 5, lane = threadIdx.x & 31;
    if (lane == 0) {
        #pragma unroll
        for (int c = 0; c < NCLS; c++) sm[warp][c] = acc[c];
    }
    __syncthreads();
    if (threadIdx.x == 0) {
        float logits[NCLS];
        float m = -1e30f;
        #pragma unroll
        for (int c = 0; c < NCLS; c++) {
            float v = sm[0][c] + sm[1][c] + sm[2][c] + sm[3][c] + b[c];
            v = fmaxf(v, 0.f);
            logits[c] = v;
            m = fmaxf(m, v);
        }
        float ssum = 0.f;
        #pragma unroll
        for (int c = 0; c < NCLS; c++) { logits[c] = expf(logits[c] - m); ssum += logits[c]; }
        float inv = 1.f / ssum;
        #pragma unroll
        for (int c = 0; c < NCLS; c++) out[(size_t)n * NCLS + c] = logits[c] * inv;
    }
}

// ---------------------------------------------------------------------------
// Launch
// ---------------------------------------------------------------------------
static inline int ceil_div(int a, int b) { return (a + b - 1) / b; }

extern "C" void kernel_launch(void* const* d_in, const int* in_sizes, int n_in,
                              void* d_out, int out_size)
{
    const float* x      = (const float*)d_in[0];
    const int*   ei     = (const int*)  d_in[1];
    const float* W0     = (const float*)d_in[2];
    const float* a_src0 = (const float*)d_in[3];
    const float* a_dst0 = (const float*)d_in[4];
    const float* b0     = (const float*)d_in[5];
    const float* W1     = (const float*)d_in[6];
    const float* a_src1 = (const float*)d_in[7];
    const float* a_dst1 = (const float*)d_in[8];
    const float* b1     = (const float*)d_in[9];
    const float* lw1    = (const float*)d_in[10];
    const float* lb1    = (const float*)d_in[11];
    const float* lw2    = (const float*)d_in[12];
    const float* lb2    = (const float*)d_in[13];
    const float* lw3    = (const float*)d_in[14];
    const float* lb3    = (const float*)d_in[15];
    float* out = (float*)d_out;

    const int Nn = in_sizes[0] / F_IN;
    const int E  = in_sizes[1] / 2;

    float *p_h, *p_t2, *p_asrc, *p_adst;
    uint32_t *p_xh, *p_xl, *p_o1h, *p_o1l, *p_o2h, *p_o2l, *p_t1h, *p_t1l;
    uint32_t *p_w0h, *p_w0l, *p_w1h, *p_w1l, *p_w2h, *p_w2l, *p_w3h, *p_w3l;
    int *p_cnt, *p_offs, *p_cur, *p_csrc;
    cudaGetSymbolAddress((void**)&p_h,    g_h);
    cudaGetSymbolAddress((void**)&p_t2,   g_t2);
    cudaGetSymbolAddress((void**)&p_asrc, g_asrc);
    cudaGetSymbolAddress((void**)&p_adst, g_adst);
    cudaGetSymbolAddress((void**)&p_xh,  g_xh);   cudaGetSymbolAddress((void**)&p_xl,  g_xl);
    cudaGetSymbolAddress((void**)&p_o1h, g_o1h);  cudaGetSymbolAddress((void**)&p_o1l, g_o1l);
    cudaGetSymbolAddress((void**)&p_o2h, g_o2h);  cudaGetSymbolAddress((void**)&p_o2l, g_o2l);
    cudaGetSymbolAddress((void**)&p_t1h, g_t1h);  cudaGetSymbolAddress((void**)&p_t1l, g_t1l);
    cudaGetSymbolAddress((void**)&p_w0h, g_w0h);  cudaGetSymbolAddress((void**)&p_w0l, g_w0l);
    cudaGetSymbolAddress((void**)&p_w1h, g_w1h);  cudaGetSymbolAddress((void**)&p_w1l, g_w1l);
    cudaGetSymbolAddress((void**)&p_w2h, g_w2h);  cudaGetSymbolAddress((void**)&p_w2l, g_w2l);
    cudaGetSymbolAddress((void**)&p_w3h, g_w3h);  cudaGetSymbolAddress((void**)&p_w3l, g_w3l);
    cudaGetSymbolAddress((void**)&p_cnt,  g_cnt);
    cudaGetSymbolAddress((void**)&p_offs, g_offs);
    cudaGetSymbolAddress((void**)&p_cur,  g_cur);
    cudaGetSymbolAddress((void**)&p_csrc, g_csrc);

    cudaFuncSetAttribute(mma_gemm, cudaFuncAttributeMaxDynamicSharedMemorySize,
                         GEMM_SMEM_BYTES);

    const int gy = ceil_div(Nn, 128);
    dim3 tb(32, 32);

    // Launches 1-3: GEMM1 prerequisites
    transpose_split_kernel<<<dim3(256 / 32, 128 / 32), tb>>>(W0, p_w0h, p_w0l, 128, 256);
    split_kernel<<<ceil_div(Nn * F_IN / 4, 256), 256>>>((const float4*)x, p_xh, p_xl,
                                                        Nn * F_IN / 4);
    transpose_split_kernel<<<dim3(256 / 32, 256 / 32), tb>>>(W1, p_w1h, p_w1l, 256, 256);
    // Launch 4 = ncu capture slot: the REAL GEMM1.
    mma_gemm<<<dim3(F0 / 128, gy), 256, GEMM_SMEM_BYTES>>>(
        Nn, F0, F_IN, p_xh, p_xl, p_w0h, p_w0l, nullptr, p_h, 0, nullptr, nullptr);

    transpose_split_kernel<<<dim3(512 / 32, 256 / 32), tb>>>(lw1, p_w2h, p_w2l, 256, 512);
    transpose_split_kernel<<<dim3(1024 / 32, 512 / 32), tb>>>(lw2, p_w3h, p_w3l, 512, 1024);

    // CSR build (reused by both layers)
    cudaMemsetAsync(p_cnt, 0, Nn * sizeof(int), 0);
    csr_count_kernel<<<ceil_div(E, 256), 256>>>(ei, E, p_cnt);
    csr_scan_kernel<<<1, 1024>>>(p_cnt, p_offs, p_cur, Nn);
    csr_scatter_kernel<<<ceil_div(E, 256), 256>>>(ei, E, p_cur, p_csrc);

    // ---------------- GAT layer 0 (GEMM1 already launched) ----------------
    alpha_init_kernel<<<ceil_div(Nn * H0 * 32, 256), 256>>>(
        p_h, a_src0, a_dst0, Nn, H0, C0, p_asrc, p_adst);
    aggregate_csr_kernel<<<ceil_div(Nn * 32, 256), 256>>>(
        p_offs, p_csrc, p_asrc, p_adst, p_h, b0, Nn, H0, 6, p_o1h, p_o1l);

    // ---------------- GAT layer 1 ----------------
    mma_gemm<<<dim3(F1 / 128, gy), 256, GEMM_SMEM_BYTES>>>(
        Nn, F1, F0, p_o1h, p_o1l, p_w1h, p_w1l, nullptr, p_h, 0, nullptr, nullptr);
    alpha_init_kernel<<<ceil_div(Nn * H1 * 32, 256), 256>>>(
        p_h, a_src1, a_dst1, Nn, H1, C1, p_asrc, p_adst);
    aggregate_csr_kernel<<<ceil_div(Nn * 32, 256), 256>>>(
        p_offs, p_csrc, p_asrc, p_adst, p_h, b1, Nn, H1, 8, p_o2h, p_o2l);

    // ---------------- MLP ----------------
    // t1: packed output only (no fp32 write needed)
    mma_gemm<<<dim3(512 / 128, gy), 256, GEMM_SMEM_BYTES>>>(
        Nn, 512, 256, p_o2h, p_o2l, p_w2h, p_w2l, lb1, nullptr, 1, p_t1h, p_t1l);
    mma_gemm<<<dim3(1024 / 128, gy), 256, GEMM_SMEM_BYTES>>>(
        Nn, 1024, 512, p_t1h, p_t1l, p_w3h, p_w3l, lb2, p_t2, 1, nullptr, nullptr);
    final_kernel<<<Nn, 128>>>(p_t2, lw3, lb3, out, 1024);
}

// round 16
// speedup vs baseline: 1.1978x; 1.1978x over previous
#include <cuda_runtime.h>
#include <math.h>
#include <stdint.h>

// ---------------------------------------------------------------------------
// Problem constants
// ---------------------------------------------------------------------------
#define NN     50000
#define EE     400000
#define F_IN   128
#define H0     4
#define C0     64
#define F0     (H0*C0)    // 256
#define H1     1
#define C1     256
#define F1     256
#define NCLS   10
#define SLOPE  0.2f

// ---------------------------------------------------------------------------
// Scratch (device globals)
// ---------------------------------------------------------------------------
__device__ float g_h   [NN * 256];
__device__ float g_out [NN * 256];
__device__ float g_out2[NN * 256];
__device__ float g_t1  [NN * 512];
__device__ float g_t2  [NN * 1024];
__device__ float g_asrc[NN * H0];
__device__ float g_adst[NN * H0];
// packed bf16x2 hi/lo transposed weights [N, K/2]
__device__ uint32_t g_w0h[256 * 64],   g_w0l[256 * 64];
__device__ uint32_t g_w1h[256 * 128],  g_w1l[256 * 128];
__device__ uint32_t g_w2h[512 * 128],  g_w2l[512 * 128];
__device__ uint32_t g_w3h[1024 * 256], g_w3l[1024 * 256];
// CSR by destination
__device__ int g_cnt [NN];
__device__ int g_offs[NN + 1];
__device__ int g_cur [NN];
__device__ int g_csrc[EE];

// ---------------------------------------------------------------------------
// helpers (baseline PTX: sm_80-era mma.sync bf16 + cp.async + ldmatrix)
// ---------------------------------------------------------------------------
__device__ __forceinline__ uint32_t pack_bf16(float hi, float lo) {
    uint32_t r;
    asm("cvt.rn.bf16x2.f32 %0, %1, %2;" : "=r"(r) : "f"(hi), "f"(lo));
    return r;
}

// split float2 (p.x = k even, p.y = k odd) into bf16x2 hi + bf16x2 residual
__device__ __forceinline__ void split2(float2 p, uint32_t& h, uint32_t& l) {
    h = pack_bf16(p.y, p.x);
    float rhi = p.y - __uint_as_float(h & 0xFFFF0000u);
    float rlo = p.x - __uint_as_float(h << 16);
    l = pack_bf16(rhi, rlo);
}

__device__ __forceinline__ void mma16(float c[4], const uint32_t a[4],
                                      uint32_t b0, uint32_t b1) {
    asm volatile(
        "mma.sync.aligned.m16n8k16.row.col.f32.bf16.bf16.f32 "
        "{%0,%1,%2,%3}, {%4,%5,%6,%7}, {%8,%9}, {%0,%1,%2,%3};"
        : "+f"(c[0]), "+f"(c[1]), "+f"(c[2]), "+f"(c[3])
        : "r"(a[0]), "r"(a[1]), "r"(a[2]), "r"(a[3]), "r"(b0), "r"(b1));
}

__device__ __forceinline__ void ldsm_x4(uint32_t& r0, uint32_t& r1,
                                        uint32_t& r2, uint32_t& r3,
                                        uint32_t addr) {
    asm volatile("ldmatrix.sync.aligned.m8n8.x4.shared.b16 {%0,%1,%2,%3}, [%4];"
                 : "=r"(r0), "=r"(r1), "=r"(r2), "=r"(r3) : "r"(addr));
}

__device__ __forceinline__ uint32_t smem_u32(const void* p) {
    uint32_t a;
    asm("{ .reg .u64 t; cvta.to.shared.u64 t, %1; cvt.u32.u64 %0, t; }"
        : "=r"(a) : "l"(p));
    return a;
}

__device__ __forceinline__ void cp16(uint32_t dst, const void* src, int srcsize) {
    asm volatile("cp.async.ca.shared.global [%0], [%1], 16, %2;"
                 :: "r"(dst), "l"(src), "r"(srcsize));
}
#define CP_COMMIT() asm volatile("cp.async.commit_group;")
#define CP_WAIT(n)  asm volatile("cp.async.wait_group %0;" :: "n"(n))

// ---------------------------------------------------------------------------
// BF16x3 tensor-core GEMM (R12 pipeline, known-good): raw fp32 A with
// smem-staged conversion x pre-split packed bf16 B (weights, no convert).
// NEW: optional fused alpha reduction in the epilogue
//   asrc[n,head] += sum_c C[n,c]*a_srcW[c],  adst likewise.
// C[M,N] = A[M,K] @ Bt[N,K]^T  (+bias, +relu)
// CTA 128x128, BK=32, 256 threads (8 warps 2x4), warp 64x32.
// Mainloop: ldmatrix.x4 + HMMA. products: ah*bh + ah*bl + al*bh.
// Raw A pitch 36 (conflict-free); packed pitch 20 (ldmatrix conflict-free).
// SMEM: rawA + pkA(single) + pkB(double) = 79872 B -> 2 CTAs/SM.
// ---------------------------------------------------------------------------
#define PADR 36
#define RAW_W (128 * PADR)            // 4608 words (raw A)
#define PADP 20
#define PK_W  (128 * PADP)            // 2560 words per packed array
#define OFF_AH   RAW_W
#define OFF_AL   (RAW_W + PK_W)
#define OFF_B0   (RAW_W + 2 * PK_W)   // stage0: hi at +0, lo at +PK_W
#define OFF_B1   (RAW_W + 4 * PK_W)   // stage1
#define GEMM_SMEM_BYTES ((RAW_W + 6 * PK_W) * 4)   // 79872 B

__global__ __launch_bounds__(256, 2)
void mma_gemm(int M, int N, int K,
              const float* __restrict__ A,          // [M,K] fp32
              const uint32_t* __restrict__ Bh_g,    // [N,K/2] packed hi
              const uint32_t* __restrict__ Bl_g,    // [N,K/2] packed lo
              const float* __restrict__ bias,
              float* __restrict__ C, int do_relu,
              int do_alpha, const float* __restrict__ a_srcW,
              const float* __restrict__ a_dstW,
              float* __restrict__ asrc, float* __restrict__ adst,
              int H, int cshift)
{
    extern __shared__ float sm[];
    uint32_t* smw = (uint32_t*)sm;
    const uint32_t smbase = smem_u32(sm);

    const int tid  = threadIdx.x;
    const int wid  = tid >> 5;
    const int lane = tid & 31;
    const int g    = lane >> 2;
    const int tig  = lane & 3;
    const int warpRow = (wid & 1) * 64;
    const int warpCol = (wid >> 1) * 32;
    const int rowBase = blockIdx.y * 128;
    const int colBase = blockIdx.x * 128;
    const int Kw = K >> 1;

    float acc[4][4][4];
    #pragma unroll
    for (int mf = 0; mf < 4; mf++)
        #pragma unroll
        for (int nf = 0; nf < 4; nf++)
            #pragma unroll
            for (int r = 0; r < 4; r++) acc[mf][nf][r] = 0.0f;

    // loader mapping: thread = (row 0..127, half 0/1)
    const int lrow = tid >> 1;
    const int half = tid & 1;
    const int lcol = half * 16;                 // fp32 col for A
    const int asz  = ((rowBase + lrow) < M) ? 16 : 0;
    const float* Ap = A + (size_t)(rowBase + lrow) * K + lcol;
    const uint32_t rawAd = smbase + (uint32_t)(lrow * PADR + lcol) * 4;
    // B packed: 16 words/row/chunk; this thread covers words half*8 .. half*8+7
    const uint32_t* Bhp = Bh_g + (size_t)(colBase + lrow) * Kw + half * 8;
    const uint32_t* Blp = Bl_g + (size_t)(colBase + lrow) * Kw + half * 8;
    const uint32_t pkBd = (uint32_t)(lrow * PADP + half * 8) * 4;

    const int nch = K / 32;

    // prologue: chunk 0 (A raw + B packed stage 0)
    {
        uint32_t b0 = smbase + (uint32_t)OFF_B0 * 4 + pkBd;
        #pragma unroll
        for (int q = 0; q < 4; q++)
            cp16(rawAd + q * 16, Ap + q * 4, asz);
        cp16(b0,      Bhp,     16); cp16(b0 + 16,          Bhp + 4, 16);
        cp16(b0 + PK_W * 4, Blp, 16); cp16(b0 + PK_W * 4 + 16, Blp + 4, 16);
        CP_COMMIT();
    }

    const float2* rpa = (const float2*)(sm + lrow * PADR + lcol);
    uint32_t* pkA = smw + OFF_AH + lrow * PADP + (lcol >> 1);

    // ldmatrix addresses
    const uint32_t aAddr = smbase + (uint32_t)OFF_AH * 4
        + (uint32_t)(warpRow + (lane & 15)) * PADP * 4 + (uint32_t)(lane >> 4) * 16;
    const uint32_t bAddr0 = smbase
        + (uint32_t)(warpCol + ((lane >> 4) * 8) + (lane & 7)) * PADP * 4
        + (uint32_t)((lane >> 3) & 1) * 16;

    for (int kc = 0; kc < nch; kc++) {
        CP_WAIT(0);
        __syncthreads();   // rawA[kc] + pkB[kc] ready; prev compute done

        // ---- convert A raw fp32 -> packed bf16 hi/lo (A only) ----
        {
            uint32_t hw[8], lw_[8];
            #pragma unroll
            for (int p = 0; p < 8; p++) split2(rpa[p], hw[p], lw_[p]);
            *(uint4*)pkA          = make_uint4(hw[0], hw[1], hw[2], hw[3]);
            *(uint4*)(pkA + 4)    = make_uint4(hw[4], hw[5], hw[6], hw[7]);
            *(uint4*)(pkA + PK_W)     = make_uint4(lw_[0], lw_[1], lw_[2], lw_[3]);
            *(uint4*)(pkA + PK_W + 4) = make_uint4(lw_[4], lw_[5], lw_[6], lw_[7]);
        }
        __syncthreads();   // pkA ready; rawA free

        // prefetch chunk kc+1 (A raw reuses the single buffer; B other stage)
        if (kc + 1 < nch) {
            const int kbA = (kc + 1) * 32;
            #pragma unroll
            for (int q = 0; q < 4; q++)
                cp16(rawAd + q * 16, Ap + kbA + q * 4, asz);
            const int kbB = (kc + 1) * 16;
            uint32_t bn = smbase
                + (uint32_t)(((kc + 1) & 1) ? OFF_B1 : OFF_B0) * 4 + pkBd;
            cp16(bn,      Bhp + kbB,     16); cp16(bn + 16,          Bhp + kbB + 4, 16);
            cp16(bn + PK_W * 4, Blp + kbB, 16); cp16(bn + PK_W * 4 + 16, Blp + kbB + 4, 16);
            CP_COMMIT();
        }

        // ---- compute: 2 K=16 steps; ldmatrix.x4 fragment loads ----
        const uint32_t bStage = (uint32_t)((kc & 1) ? OFF_B1 : OFF_B0) * 4;
        #pragma unroll
        for (int ks = 0; ks < 2; ks++) {
            const uint32_t ko = (uint32_t)ks * 32;  // 8 packed words = 32B
            uint32_t ah[4][4], al[4][4];
            #pragma unroll
            for (int mf = 0; mf < 4; mf++) {
                uint32_t a = aAddr + (uint32_t)mf * (16 * PADP * 4) + ko;
                ldsm_x4(ah[mf][0], ah[mf][1], ah[mf][2], ah[mf][3], a);
                ldsm_x4(al[mf][0], al[mf][1], al[mf][2], al[mf][3], a + PK_W * 4);
            }
            #pragma unroll
            for (int p = 0; p < 2; p++) {
                uint32_t b = bAddr0 + bStage + (uint32_t)p * (16 * PADP * 4) + ko;
                uint32_t bh0a, bh1a, bh0b, bh1b;
                uint32_t bl0a, bl1a, bl0b, bl1b;
                ldsm_x4(bh0a, bh1a, bh0b, bh1b, b);
                ldsm_x4(bl0a, bl1a, bl0b, bl1b, b + PK_W * 4);
                const int nf0 = 2 * p, nf1 = 2 * p + 1;
                #pragma unroll
                for (int mf = 0; mf < 4; mf++) {
                    mma16(acc[mf][nf0], ah[mf], bh0a, bh1a);
                    mma16(acc[mf][nf0], ah[mf], bl0a, bl1a);
                    mma16(acc[mf][nf0], al[mf], bh0a, bh1a);
                    mma16(acc[mf][nf1], ah[mf], bh0b, bh1b);
                    mma16(acc[mf][nf1], ah[mf], bl0b, bl1b);
                    mma16(acc[mf][nf1], al[mf], bh0b, bh1b);
                }
            }
        }
    }

    // ---- stage alpha weight slices (reuse rawA area; free after loop) ----
    if (do_alpha) {
        __syncthreads();      // all compute done before reusing smem
        if (tid < 32) {
            float4 va = *(const float4*)(a_srcW + colBase + tid * 4);
            float4 vd = *(const float4*)(a_dstW + colBase + tid * 4);
            *(float4*)&sm[tid * 4]       = va;
            *(float4*)&sm[128 + tid * 4] = vd;
        }
        __syncthreads();
    }

    // ---- epilogue (+ fused alpha reduction) ----
    #pragma unroll
    for (int mf = 0; mf < 4; mf++) {
        int r0 = rowBase + warpRow + mf * 16 + g;
        int r1 = r0 + 8;
        float ps0 = 0.f, pd0 = 0.f, ps1 = 0.f, pd1 = 0.f;
        #pragma unroll
        for (int nf = 0; nf < 4; nf++) {
            int cl  = warpCol + nf * 8 + tig * 2;   // CTA-local col
            int col = colBase + cl;
            float b0v = 0.f, b1v = 0.f;
            if (bias) { b0v = bias[col]; b1v = bias[col + 1]; }
            float2 v0 = make_float2(acc[mf][nf][0] + b0v, acc[mf][nf][1] + b1v);
            float2 v1 = make_float2(acc[mf][nf][2] + b0v, acc[mf][nf][3] + b1v);
            if (do_relu) {
                v0.x = fmaxf(v0.x, 0.f); v0.y = fmaxf(v0.y, 0.f);
                v1.x = fmaxf(v1.x, 0.f); v1.y = fmaxf(v1.y, 0.f);
            }
            if (do_alpha) {
                float2 asv = *(const float2*)&sm[cl];
                float2 adv = *(const float2*)&sm[128 + cl];
                ps0 = fmaf(v0.x, asv.x, fmaf(v0.y, asv.y, ps0));
                pd0 = fmaf(v0.x, adv.x, fmaf(v0.y, adv.y, pd0));
                ps1 = fmaf(v1.x, asv.x, fmaf(v1.y, asv.y, ps1));
                pd1 = fmaf(v1.x, adv.x, fmaf(v1.y, adv.y, pd1));
            }
            if (r0 < M) *(float2*)&C[(size_t)r0 * N + col] = v0;
            if (r1 < M) *(float2*)&C[(size_t)r1 * N + col] = v1;
        }
        if (do_alpha) {
            ps0 += __shfl_xor_sync(0xffffffffu, ps0, 1);
            ps0 += __shfl_xor_sync(0xffffffffu, ps0, 2);
            pd0 += __shfl_xor_sync(0xffffffffu, pd0, 1);
            pd0 += __shfl_xor_sync(0xffffffffu, pd0, 2);
            ps1 += __shfl_xor_sync(0xffffffffu, ps1, 1);
            ps1 += __shfl_xor_sync(0xffffffffu, ps1, 2);
            pd1 += __shfl_xor_sync(0xffffffffu, pd1, 1);
            pd1 += __shfl_xor_sync(0xffffffffu, pd1, 2);
            if (tig == 0) {
                int head = (colBase + warpCol) >> cshift;
                if (r0 < M) {
                    atomicAdd(&asrc[r0 * H + head], ps0);
                    atomicAdd(&adst[r0 * H + head], pd0);
                }
                if (r1 < M) {
                    atomicAdd(&asrc[r1 * H + head], ps1);
                    atomicAdd(&adst[r1 * H + head], pd1);
                }
            }
        }
    }
}

// ---------------------------------------------------------------------------
// Weight transpose + bf16 split: W[K,N] -> packed hi/lo [N, K/2]
// ---------------------------------------------------------------------------
__global__ void transpose_split_kernel(const float* __restrict__ W,
                                       uint32_t* __restrict__ oh,
                                       uint32_t* __restrict__ ol, int K, int N)
{
    __shared__ float t[32][33];
    int kb = blockIdx.y * 32, nb = blockIdx.x * 32;
    int tx = threadIdx.x, ty = threadIdx.y;
    t[ty][tx] = W[(size_t)(kb + ty) * N + nb + tx];
    __syncthreads();
    if (tx < 16) {
        int n2 = nb + ty;
        int kp = (kb >> 1) + tx;
        uint32_t h, l;
        split2(make_float2(t[2 * tx][ty], t[2 * tx + 1][ty]), h, l);
        oh[(size_t)n2 * (K >> 1) + kp] = h;
        ol[(size_t)n2 * (K >> 1) + kp] = l;
    }
}

// ---------------------------------------------------------------------------
// CSR build
// ---------------------------------------------------------------------------
__global__ void csr_count_kernel(const int* __restrict__ ei, int E,
                                 int* __restrict__ cnt)
{
    int i = blockIdx.x * blockDim.x + threadIdx.x;
    if (i < E) atomicAdd(&cnt[ei[E + i]], 1);
}

__global__ __launch_bounds__(1024) void csr_scan_kernel(
    const int* __restrict__ cnt, int* __restrict__ offs,
    int* __restrict__ cur, int n)
{
    __shared__ int smbuf[1024];
    __shared__ int carry;
    if (threadIdx.x == 0) { carry = 0; offs[0] = 0; }
    __syncthreads();
    for (int base = 0; base < n; base += 1024) {
        int i = base + threadIdx.x;
        int v = (i < n) ? cnt[i] : 0;
        smbuf[threadIdx.x] = v;
        __syncthreads();
        #pragma unroll
        for (int off = 1; off < 1024; off <<= 1) {
            int t = (threadIdx.x >= off) ? smbuf[threadIdx.x - off] : 0;
            __syncthreads();
            smbuf[threadIdx.x] += t;
            __syncthreads();
        }
        if (i < n) {
            int inc = carry + smbuf[threadIdx.x];
            offs[i + 1] = inc;
            cur[i] = inc - v;
        }
        __syncthreads();
        if (threadIdx.x == 0) carry += smbuf[1023];
        __syncthreads();
    }
}

__global__ void csr_scatter_kernel(const int* __restrict__ ei, int E,
                                   int* __restrict__ cur,
                                   int* __restrict__ csrc)
{
    int i = blockIdx.x * blockDim.x + threadIdx.x;
    if (i >= E) return;
    int d = ei[E + i];
    int p = atomicAdd(&cur[d], 1);
    csrc[p] = ei[i];
}

// ---------------------------------------------------------------------------
// Fused CSR aggregation: attention weights inline, no atomics, fp32 out.
// One warp per destination node; F = 256.
// ---------------------------------------------------------------------------
__global__ void aggregate_csr_kernel(
    const int* __restrict__ offs, const int* __restrict__ csrc,
    const float* __restrict__ asrc, const float* __restrict__ adst,
    const float* __restrict__ hfeat, const float* __restrict__ bias,
    int Nn, int H, int cshift, float* __restrict__ out)
{
    int node = (blockIdx.x * blockDim.x + threadIdx.x) >> 5;
    int lane = threadIdx.x & 31;
    if (node >= Nn) return;
    const int hsel = (H > 1) ? (lane >> (cshift - 3)) : 0;

    const float adn = adst[node * H + hsel];

    float v = asrc[node * H + hsel] + adn;
    float w = expf((v > 0.f) ? v : SLOPE * v);
    float wsum = w;
    const float4* hp = (const float4*)(hfeat + (size_t)node * 256 + lane * 8);
    float4 u = hp[0], vv4 = hp[1];
    float a0 = w * u.x,   a1 = w * u.y,   a2 = w * u.z,   a3 = w * u.w;
    float a4 = w * vv4.x, a5 = w * vv4.y, a6 = w * vv4.z, a7 = w * vv4.w;

    const int e1 = offs[node + 1];
    for (int e = offs[node]; e < e1; e++) {
        int s = csrc[e];
        if (s != node) {
            float ve = asrc[s * H + hsel] + adn;
            float we = expf((ve > 0.f) ? ve : SLOPE * ve);
            wsum += we;
            const float4* sp = (const float4*)(hfeat + (size_t)s * 256 + lane * 8);
            float4 p = sp[0], q = sp[1];
            a0 = fmaf(we, p.x, a0); a1 = fmaf(we, p.y, a1);
            a2 = fmaf(we, p.z, a2); a3 = fmaf(we, p.w, a3);
            a4 = fmaf(we, q.x, a4); a5 = fmaf(we, q.y, a5);
            a6 = fmaf(we, q.z, a6); a7 = fmaf(we, q.w, a7);
        }
    }

    const float inv = 1.0f / wsum;
    const int colb = lane * 8;
    float4 o0, o1v;
    o0.x  = fmaxf(fmaf(a0, inv, bias[colb + 0]), 0.f);
    o0.y  = fmaxf(fmaf(a1, inv, bias[colb + 1]), 0.f);
    o0.z  = fmaxf(fmaf(a2, inv, bias[colb + 2]), 0.f);
    o0.w  = fmaxf(fmaf(a3, inv, bias[colb + 3]), 0.f);
    o1v.x = fmaxf(fmaf(a4, inv, bias[colb + 4]), 0.f);
    o1v.y = fmaxf(fmaf(a5, inv, bias[colb + 5]), 0.f);
    o1v.z = fmaxf(fmaf(a6, inv, bias[colb + 6]), 0.f);
    o1v.w = fmaxf(fmaf(a7, inv, bias[colb + 7]), 0.f);
    float4* op = (float4*)(out + (size_t)node * 256 + colb);
    op[0] = o0;
    op[1] = o1v;
}

// ---------------------------------------------------------------------------
// Final: out = softmax(relu(X @ lw3 + lb3)), X:[N,1024]
// ---------------------------------------------------------------------------
__global__ __launch_bounds__(128) void final_kernel(
    const float* __restrict__ X, const float* __restrict__ W,
    const float* __restrict__ b, float* __restrict__ out, int K)
{
    int n = blockIdx.x;
    const float* x = X + (size_t)n * K;

    float acc[NCLS];
    #pragma unroll
    for (int c = 0; c < NCLS; c++) acc[c] = 0.f;

    for (int k = threadIdx.x; k < K; k += 128) {
        float xv = x[k];
        const float* wr = W + (size_t)k * NCLS;
        #pragma unroll
        for (int c = 0; c < NCLS; c++) acc[c] = fmaf(xv, wr[c], acc[c]);
    }
    #pragma unroll
    for (int c = 0; c < NCLS; c++)
        #pragma unroll
        for (int off = 16; off; off >>= 1)
            acc[c] += __shfl_xor_sync(0xffffffffu, acc[c], off);

    __shared__ float smf[4][NCLS];
    int warp = threadIdx.x >> 5, lane = threadIdx.x & 31;
    if (lane == 0) {
        #pragma unroll
        for (int c = 0; c < NCLS; c++) smf[warp][c] = acc[c];
    }
    __syncthreads();
    if (threadIdx.x == 0) {
        float logits[NCLS];
        float m = -1e30f;
        #pragma unroll
        for (int c = 0; c < NCLS; c++) {
            float v = smf[0][c] + smf[1][c] + smf[2][c] + smf[3][c] + b[c];
            v = fmaxf(v, 0.f);
            logits[c] = v;
            m = fmaxf(m, v);
        }
        float ssum = 0.f;
        #pragma unroll
        for (int c = 0; c < NCLS; c++) { logits[c] = expf(logits[c] - m); ssum += logits[c]; }
        float inv = 1.f / ssum;
        #pragma unroll
        for (int c = 0; c < NCLS; c++) out[(size_t)n * NCLS + c] = logits[c] * inv;
    }
}

// ---------------------------------------------------------------------------
// Launch
// ---------------------------------------------------------------------------
static inline int ceil_div(int a, int b) { return (a + b - 1) / b; }

extern "C" void kernel_launch(void* const* d_in, const int* in_sizes, int n_in,
                              void* d_out, int out_size)
{
    const float* x      = (const float*)d_in[0];
    const int*   ei     = (const int*)  d_in[1];
    const float* W0     = (const float*)d_in[2];
    const float* a_src0 = (const float*)d_in[3];
    const float* a_dst0 = (const float*)d_in[4];
    const float* b0     = (const float*)d_in[5];
    const float* W1     = (const float*)d_in[6];
    const float* a_src1 = (const float*)d_in[7];
    const float* a_dst1 = (const float*)d_in[8];
    const float* b1     = (const float*)d_in[9];
    const float* lw1    = (const float*)d_in[10];
    const float* lb1    = (const float*)d_in[11];
    const float* lw2    = (const float*)d_in[12];
    const float* lb2    = (const float*)d_in[13];
    const float* lw3    = (const float*)d_in[14];
    const float* lb3    = (const float*)d_in[15];
    float* out = (float*)d_out;

    const int Nn = in_sizes[0] / F_IN;
    const int E  = in_sizes[1] / 2;

    float *p_h, *p_out, *p_out2, *p_t1, *p_t2, *p_asrc, *p_adst;
    uint32_t *p_w0h, *p_w0l, *p_w1h, *p_w1l, *p_w2h, *p_w2l, *p_w3h, *p_w3l;
    int *p_cnt, *p_offs, *p_cur, *p_csrc;
    cudaGetSymbolAddress((void**)&p_h,    g_h);
    cudaGetSymbolAddress((void**)&p_out,  g_out);
    cudaGetSymbolAddress((void**)&p_out2, g_out2);
    cudaGetSymbolAddress((void**)&p_t1,   g_t1);
    cudaGetSymbolAddress((void**)&p_t2,   g_t2);
    cudaGetSymbolAddress((void**)&p_asrc, g_asrc);
    cudaGetSymbolAddress((void**)&p_adst, g_adst);
    cudaGetSymbolAddress((void**)&p_w0h, g_w0h);  cudaGetSymbolAddress((void**)&p_w0l, g_w0l);
    cudaGetSymbolAddress((void**)&p_w1h, g_w1h);  cudaGetSymbolAddress((void**)&p_w1l, g_w1l);
    cudaGetSymbolAddress((void**)&p_w2h, g_w2h);  cudaGetSymbolAddress((void**)&p_w2l, g_w2l);
    cudaGetSymbolAddress((void**)&p_w3h, g_w3h);  cudaGetSymbolAddress((void**)&p_w3l, g_w3l);
    cudaGetSymbolAddress((void**)&p_cnt,  g_cnt);
    cudaGetSymbolAddress((void**)&p_offs, g_offs);
    cudaGetSymbolAddress((void**)&p_cur,  g_cur);
    cudaGetSymbolAddress((void**)&p_csrc, g_csrc);

    cudaFuncSetAttribute(mma_gemm, cudaFuncAttributeMaxDynamicSharedMemorySize,
                         GEMM_SMEM_BYTES);

    const int gy = ceil_div(Nn, 128);
    dim3 tb(32, 32);

    // zero alpha accumulators for layer 0
    cudaMemsetAsync(p_asrc, 0, (size_t)Nn * H0 * sizeof(float), 0);
    cudaMemsetAsync(p_adst, 0, (size_t)Nn * H0 * sizeof(float), 0);

    transpose_split_kernel<<<dim3(256 / 32, 128 / 32), tb>>>(W0,  p_w0h, p_w0l, 128, 256);
    transpose_split_kernel<<<dim3(256 / 32, 256 / 32), tb>>>(W1,  p_w1h, p_w1l, 256, 256);
    transpose_split_kernel<<<dim3(512 / 32, 256 / 32), tb>>>(lw1, p_w2h, p_w2l, 256, 512);
    // GEMM1 (h0 = x @ W0, fused alpha for layer 0)
    mma_gemm<<<dim3(F0 / 128, gy), 256, GEMM_SMEM_BYTES>>>(
        Nn, F0, F_IN, x, p_w0h, p_w0l, nullptr, p_h, 0,
        1, a_src0, a_dst0, p_asrc, p_adst, H0, 6);

    transpose_split_kernel<<<dim3(1024 / 32, 512 / 32), tb>>>(lw2, p_w3h, p_w3l, 512, 1024);

    // CSR build (reused by both layers)
    cudaMemsetAsync(p_cnt, 0, Nn * sizeof(int), 0);
    csr_count_kernel<<<ceil_div(E, 256), 256>>>(ei, E, p_cnt);
    csr_scan_kernel<<<1, 1024>>>(p_cnt, p_offs, p_cur, Nn);
    csr_scatter_kernel<<<ceil_div(E, 256), 256>>>(ei, E, p_cur, p_csrc);

    // ---------------- GAT layer 0 (GEMM1 + alpha already done) ------------
    aggregate_csr_kernel<<<ceil_div(Nn * 32, 256), 256>>>(
        p_offs, p_csrc, p_asrc, p_adst, p_h, b0, Nn, H0, 6, p_out);

    // ---------------- GAT layer 1 ----------------
    cudaMemsetAsync(p_asrc, 0, (size_t)Nn * H1 * sizeof(float), 0);
    cudaMemsetAsync(p_adst, 0, (size_t)Nn * H1 * sizeof(float), 0);
    mma_gemm<<<dim3(F1 / 128, gy), 256, GEMM_SMEM_BYTES>>>(
        Nn, F1, F0, p_out, p_w1h, p_w1l, nullptr, p_h, 0,
        1, a_src1, a_dst1, p_asrc, p_adst, H1, 8);
    aggregate_csr_kernel<<<ceil_div(Nn * 32, 256), 256>>>(
        p_offs, p_csrc, p_asrc, p_adst, p_h, b1, Nn, H1, 8, p_out2);

    // ---------------- MLP ----------------
    mma_gemm<<<dim3(512 / 128, gy), 256, GEMM_SMEM_BYTES>>>(
        Nn, 512, 256, p_out2, p_w2h, p_w2l, lb1, p_t1, 1,
        0, nullptr, nullptr, nullptr, nullptr, 1, 8);
    mma_gemm<<<dim3(1024 / 128, gy), 256, GEMM_SMEM_BYTES>>>(
        Nn, 1024, 512, p_t1, p_w3h, p_w3l, lb2, p_t2, 1,
        0, nullptr, nullptr, nullptr, nullptr, 1, 8);
    final_kernel<<<Nn, 128>>>(p_t2, lw3, lb3, out, 1024);
}

// round 17
// speedup vs baseline: 1.3207x; 1.1026x over previous
#include <cuda_runtime.h>
#include <math.h>
#include <stdint.h>

// ---------------------------------------------------------------------------
// Problem constants
// ---------------------------------------------------------------------------
#define NN     50000
#define EE     400000
#define F_IN   128
#define H0     4
#define C0     64
#define F0     (H0*C0)    // 256
#define H1     1
#define C1     256
#define F1     256
#define NCLS   10
#define SLOPE  0.2f

// ---------------------------------------------------------------------------
// Scratch (device globals)
// ---------------------------------------------------------------------------
__device__ float g_h   [NN * 256];
__device__ float g_out [NN * 256];
__device__ float g_out2[NN * 256];
__device__ float g_t1  [NN * 512];
__device__ float g_asrc[NN * H0];
__device__ float g_adst[NN * H0];
// packed bf16x2 hi/lo transposed weights [N, K/2]
__device__ uint32_t g_w0h[256 * 64],   g_w0l[256 * 64];
__device__ uint32_t g_w1h[256 * 128],  g_w1l[256 * 128];
__device__ uint32_t g_w2h[512 * 128],  g_w2l[512 * 128];
__device__ uint32_t g_w3h[1024 * 256], g_w3l[1024 * 256];
// CSR by destination
__device__ int g_cnt [NN];
__device__ int g_offs[NN + 1];
__device__ int g_cur [NN];
__device__ int g_csrc[EE];

// ---------------------------------------------------------------------------
// helpers (baseline PTX: sm_80-era mma.sync bf16 + cp.async + ldmatrix)
// ---------------------------------------------------------------------------
__device__ __forceinline__ uint32_t pack_bf16(float hi, float lo) {
    uint32_t r;
    asm("cvt.rn.bf16x2.f32 %0, %1, %2;" : "=r"(r) : "f"(hi), "f"(lo));
    return r;
}

// split float2 (p.x = k even, p.y = k odd) into bf16x2 hi + bf16x2 residual
__device__ __forceinline__ void split2(float2 p, uint32_t& h, uint32_t& l) {
    h = pack_bf16(p.y, p.x);
    float rhi = p.y - __uint_as_float(h & 0xFFFF0000u);
    float rlo = p.x - __uint_as_float(h << 16);
    l = pack_bf16(rhi, rlo);
}

__device__ __forceinline__ void mma16(float c[4], const uint32_t a[4],
                                      uint32_t b0, uint32_t b1) {
    asm volatile(
        "mma.sync.aligned.m16n8k16.row.col.f32.bf16.bf16.f32 "
        "{%0,%1,%2,%3}, {%4,%5,%6,%7}, {%8,%9}, {%0,%1,%2,%3};"
        : "+f"(c[0]), "+f"(c[1]), "+f"(c[2]), "+f"(c[3])
        : "r"(a[0]), "r"(a[1]), "r"(a[2]), "r"(a[3]), "r"(b0), "r"(b1));
}

__device__ __forceinline__ void ldsm_x4(uint32_t& r0, uint32_t& r1,
                                        uint32_t& r2, uint32_t& r3,
                                        uint32_t addr) {
    asm volatile("ldmatrix.sync.aligned.m8n8.x4.shared.b16 {%0,%1,%2,%3}, [%4];"
                 : "=r"(r0), "=r"(r1), "=r"(r2), "=r"(r3) : "r"(addr));
}

__device__ __forceinline__ uint32_t smem_u32(const void* p) {
    uint32_t a;
    asm("{ .reg .u64 t; cvta.to.shared.u64 t, %1; cvt.u32.u64 %0, t; }"
        : "=r"(a) : "l"(p));
    return a;
}

__device__ __forceinline__ void cp16(uint32_t dst, const void* src, int srcsize) {
    asm volatile("cp.async.ca.shared.global [%0], [%1], 16, %2;"
                 :: "r"(dst), "l"(src), "r"(srcsize));
}
#define CP_COMMIT() asm volatile("cp.async.commit_group;")
#define CP_WAIT(n)  asm volatile("cp.async.wait_group %0;" :: "n"(n))

// ---------------------------------------------------------------------------
// BF16x3 tensor-core GEMM (R12 pipeline): raw fp32 A with smem-staged
// conversion x pre-split packed bf16 B (weights, no convert).
// Fusions (mutually exclusive):
//   do_alpha: asrc[n,head] += sum_c C[n,c]*a_srcW[c] (GAT layers)
//   do_final: logits[n,c10] += sum_col relu(C[n,col])*w3[col,c10]
//             (C not written to global at all)
// CTA 128x128, BK=32, 256 threads (8 warps 2x4), warp 64x32.
// Mainloop: ldmatrix.x4 + HMMA. products: ah*bh + ah*bl + al*bh.
// SMEM: rawA + pkA(single) + pkB(double) = 79872 B -> 2 CTAs/SM.
// ---------------------------------------------------------------------------
#define PADR 36
#define RAW_W (128 * PADR)            // 4608 words (raw A)
#define PADP 20
#define PK_W  (128 * PADP)            // 2560 words per packed array
#define OFF_AH   RAW_W
#define OFF_AL   (RAW_W + PK_W)
#define OFF_B0   (RAW_W + 2 * PK_W)   // stage0: hi at +0, lo at +PK_W
#define OFF_B1   (RAW_W + 4 * PK_W)   // stage1
#define GEMM_SMEM_BYTES ((RAW_W + 6 * PK_W) * 4)   // 79872 B

__global__ __launch_bounds__(256, 2)
void mma_gemm(int M, int N, int K,
              const float* __restrict__ A,          // [M,K] fp32
              const uint32_t* __restrict__ Bh_g,    // [N,K/2] packed hi
              const uint32_t* __restrict__ Bl_g,    // [N,K/2] packed lo
              const float* __restrict__ bias,
              float* __restrict__ C, int do_relu,
              int do_alpha, const float* __restrict__ a_srcW,
              const float* __restrict__ a_dstW,
              float* __restrict__ asrc, float* __restrict__ adst,
              int H, int cshift,
              int do_final, const float* __restrict__ w3,
              float* __restrict__ logits)
{
    extern __shared__ float sm[];
    uint32_t* smw = (uint32_t*)sm;
    const uint32_t smbase = smem_u32(sm);

    const int tid  = threadIdx.x;
    const int wid  = tid >> 5;
    const int lane = tid & 31;
    const int g    = lane >> 2;
    const int tig  = lane & 3;
    const int warpRow = (wid & 1) * 64;
    const int warpCol = (wid >> 1) * 32;
    const int rowBase = blockIdx.y * 128;
    const int colBase = blockIdx.x * 128;
    const int Kw = K >> 1;

    float acc[4][4][4];
    #pragma unroll
    for (int mf = 0; mf < 4; mf++)
        #pragma unroll
        for (int nf = 0; nf < 4; nf++)
            #pragma unroll
            for (int r = 0; r < 4; r++) acc[mf][nf][r] = 0.0f;

    // loader mapping: thread = (row 0..127, half 0/1)
    const int lrow = tid >> 1;
    const int half = tid & 1;
    const int lcol = half * 16;                 // fp32 col for A
    const int asz  = ((rowBase + lrow) < M) ? 16 : 0;
    const float* Ap = A + (size_t)(rowBase + lrow) * K + lcol;
    const uint32_t rawAd = smbase + (uint32_t)(lrow * PADR + lcol) * 4;
    const uint32_t* Bhp = Bh_g + (size_t)(colBase + lrow) * Kw + half * 8;
    const uint32_t* Blp = Bl_g + (size_t)(colBase + lrow) * Kw + half * 8;
    const uint32_t pkBd = (uint32_t)(lrow * PADP + half * 8) * 4;

    const int nch = K / 32;

    // prologue: chunk 0 (A raw + B packed stage 0)
    {
        uint32_t b0 = smbase + (uint32_t)OFF_B0 * 4 + pkBd;
        #pragma unroll
        for (int q = 0; q < 4; q++)
            cp16(rawAd + q * 16, Ap + q * 4, asz);
        cp16(b0,      Bhp,     16); cp16(b0 + 16,          Bhp + 4, 16);
        cp16(b0 + PK_W * 4, Blp, 16); cp16(b0 + PK_W * 4 + 16, Blp + 4, 16);
        CP_COMMIT();
    }

    const float2* rpa = (const float2*)(sm + lrow * PADR + lcol);
    uint32_t* pkA = smw + OFF_AH + lrow * PADP + (lcol >> 1);

    // ldmatrix addresses
    const uint32_t aAddr = smbase + (uint32_t)OFF_AH * 4
        + (uint32_t)(warpRow + (lane & 15)) * PADP * 4 + (uint32_t)(lane >> 4) * 16;
    const uint32_t bAddr0 = smbase
        + (uint32_t)(warpCol + ((lane >> 4) * 8) + (lane & 7)) * PADP * 4
        + (uint32_t)((lane >> 3) & 1) * 16;

    for (int kc = 0; kc < nch; kc++) {
        CP_WAIT(0);
        __syncthreads();   // rawA[kc] + pkB[kc] ready; prev compute done

        // ---- convert A raw fp32 -> packed bf16 hi/lo (A only) ----
        {
            uint32_t hw[8], lw_[8];
            #pragma unroll
            for (int p = 0; p < 8; p++) split2(rpa[p], hw[p], lw_[p]);
            *(uint4*)pkA          = make_uint4(hw[0], hw[1], hw[2], hw[3]);
            *(uint4*)(pkA + 4)    = make_uint4(hw[4], hw[5], hw[6], hw[7]);
            *(uint4*)(pkA + PK_W)     = make_uint4(lw_[0], lw_[1], lw_[2], lw_[3]);
            *(uint4*)(pkA + PK_W + 4) = make_uint4(lw_[4], lw_[5], lw_[6], lw_[7]);
        }
        __syncthreads();   // pkA ready; rawA free

        // prefetch chunk kc+1 (A raw reuses the single buffer; B other stage)
        if (kc + 1 < nch) {
            const int kbA = (kc + 1) * 32;
            #pragma unroll
            for (int q = 0; q < 4; q++)
                cp16(rawAd + q * 16, Ap + kbA + q * 4, asz);
            const int kbB = (kc + 1) * 16;
            uint32_t bn = smbase
                + (uint32_t)(((kc + 1) & 1) ? OFF_B1 : OFF_B0) * 4 + pkBd;
            cp16(bn,      Bhp + kbB,     16); cp16(bn + 16,          Bhp + kbB + 4, 16);
            cp16(bn + PK_W * 4, Blp + kbB, 16); cp16(bn + PK_W * 4 + 16, Blp + kbB + 4, 16);
            CP_COMMIT();
        }

        // ---- compute: 2 K=16 steps; ldmatrix.x4 fragment loads ----
        const uint32_t bStage = (uint32_t)((kc & 1) ? OFF_B1 : OFF_B0) * 4;
        #pragma unroll
        for (int ks = 0; ks < 2; ks++) {
            const uint32_t ko = (uint32_t)ks * 32;  // 8 packed words = 32B
            uint32_t ah[4][4], al[4][4];
            #pragma unroll
            for (int mf = 0; mf < 4; mf++) {
                uint32_t a = aAddr + (uint32_t)mf * (16 * PADP * 4) + ko;
                ldsm_x4(ah[mf][0], ah[mf][1], ah[mf][2], ah[mf][3], a);
                ldsm_x4(al[mf][0], al[mf][1], al[mf][2], al[mf][3], a + PK_W * 4);
            }
            #pragma unroll
            for (int p = 0; p < 2; p++) {
                uint32_t b = bAddr0 + bStage + (uint32_t)p * (16 * PADP * 4) + ko;
                uint32_t bh0a, bh1a, bh0b, bh1b;
                uint32_t bl0a, bl1a, bl0b, bl1b;
                ldsm_x4(bh0a, bh1a, bh0b, bh1b, b);
                ldsm_x4(bl0a, bl1a, bl0b, bl1b, b + PK_W * 4);
                const int nf0 = 2 * p, nf1 = 2 * p + 1;
                #pragma unroll
                for (int mf = 0; mf < 4; mf++) {
                    mma16(acc[mf][nf0], ah[mf], bh0a, bh1a);
                    mma16(acc[mf][nf0], ah[mf], bl0a, bl1a);
                    mma16(acc[mf][nf0], al[mf], bh0a, bh1a);
                    mma16(acc[mf][nf1], ah[mf], bh0b, bh1b);
                    mme_dummy:
                    mma16(acc[mf][nf1], ah[mf], bl0b, bl1b);
                    mma16(acc[mf][nf1], al[mf], bh0b, bh1b);
                }
            }
        }
    }

    // ---- stage fusion weight slices (reuse rawA area; free after loop) ----
    if (do_alpha) {
        __syncthreads();
        if (tid < 32) {
            float4 va = *(const float4*)(a_srcW + colBase + tid * 4);
            float4 vd = *(const float4*)(a_dstW + colBase + tid * 4);
            *(float4*)&sm[tid * 4]       = va;
            *(float4*)&sm[128 + tid * 4] = vd;
        }
        __syncthreads();
    }
    if (do_final) {
        __syncthreads();
        if (tid < 128) {
            const float* wr = w3 + (size_t)(colBase + tid) * NCLS;
            #pragma unroll
            for (int c = 0; c < NCLS; c++) sm[tid * NCLS + c] = wr[c];
        }
        __syncthreads();
    }

    // ---- epilogue (+ fused alpha / final reductions) ----
    #pragma unroll
    for (int mf = 0; mf < 4; mf++) {
        int r0 = rowBase + warpRow + mf * 16 + g;
        int r1 = r0 + 8;
        float ps0 = 0.f, pd0 = 0.f, ps1 = 0.f, pd1 = 0.f;
        float f0[NCLS], f1[NCLS];
        if (do_final) {
            #pragma unroll
            for (int c = 0; c < NCLS; c++) { f0[c] = 0.f; f1[c] = 0.f; }
        }
        #pragma unroll
        for (int nf = 0; nf < 4; nf++) {
            int cl  = warpCol + nf * 8 + tig * 2;   // CTA-local col
            int col = colBase + cl;
            float b0v = 0.f, b1v = 0.f;
            if (bias) { b0v = bias[col]; b1v = bias[col + 1]; }
            float2 v0 = make_float2(acc[mf][nf][0] + b0v, acc[mf][nf][1] + b1v);
            float2 v1 = make_float2(acc[mf][nf][2] + b0v, acc[mf][nf][3] + b1v);
            if (do_relu) {
                v0.x = fmaxf(v0.x, 0.f); v0.y = fmaxf(v0.y, 0.f);
                v1.x = fmaxf(v1.x, 0.f); v1.y = fmaxf(v1.y, 0.f);
            }
            if (do_alpha) {
                float2 asv = *(const float2*)&sm[cl];
                float2 adv = *(const float2*)&sm[128 + cl];
                ps0 = fmaf(v0.x, asv.x, fmaf(v0.y, asv.y, ps0));
                pd0 = fmaf(v0.x, adv.x, fmaf(v0.y, adv.y, pd0));
                ps1 = fmaf(v1.x, asv.x, fmaf(v1.y, asv.y, ps1));
                pd1 = fmaf(v1.x, adv.x, fmaf(v1.y, adv.y, pd1));
            }
            if (do_final) {
                const float* w0s = &sm[cl * NCLS];
                const float* w1s = &sm[(cl + 1) * NCLS];
                #pragma unroll
                for (int c = 0; c < NCLS; c++) {
                    f0[c] = fmaf(v0.x, w0s[c], fmaf(v0.y, w1s[c], f0[c]));
                    f1[c] = fmaf(v1.x, w0s[c], fmaf(v1.y, w1s[c], f1[c]));
                }
            }
            if (C) {
                if (r0 < M) *(float2*)&C[(size_t)r0 * N + col] = v0;
                if (r1 < M) *(float2*)&C[(size_t)r1 * N + col] = v1;
            }
        }
        if (do_alpha) {
            ps0 += __shfl_xor_sync(0xffffffffu, ps0, 1);
            ps0 += __shfl_xor_sync(0xffffffffu, ps0, 2);
            pd0 += __shfl_xor_sync(0xffffffffu, pd0, 1);
            pd0 += __shfl_xor_sync(0xffffffffu, pd0, 2);
            ps1 += __shfl_xor_sync(0xffffffffu, ps1, 1);
            ps1 += __shfl_xor_sync(0xffffffffu, ps1, 2);
            pd1 += __shfl_xor_sync(0xffffffffu, pd1, 1);
            pd1 += __shfl_xor_sync(0xffffffffu, pd1, 2);
            if (tig == 0) {
                int head = (colBase + warpCol) >> cshift;
                if (r0 < M) {
                    atomicAdd(&asrc[r0 * H + head], ps0);
                    atomicAdd(&adst[r0 * H + head], pd0);
                }
                if (r1 < M) {
                    atomicAdd(&asrc[r1 * H + head], ps1);
                    atomicAdd(&adst[r1 * H + head], pd1);
                }
            }
        }
        if (do_final) {
            #pragma unroll
            for (int c = 0; c < NCLS; c++) {
                f0[c] += __shfl_xor_sync(0xffffffffu, f0[c], 1);
                f0[c] += __shfl_xor_sync(0xffffffffu, f0[c], 2);
                f1[c] += __shfl_xor_sync(0xffffffffu, f1[c], 1);
                f1[c] += __shfl_xor_sync(0xffffffffu, f1[c], 2);
            }
            if (tig == 0) {
                if (r0 < M) {
                    #pragma unroll
                    for (int c = 0; c < NCLS; c++)
                        atomicAdd(&logits[(size_t)r0 * NCLS + c], f0[c]);
                }
                if (r1 < M) {
                    #pragma unroll
                    for (int c = 0; c < NCLS; c++)
                        atomicAdd(&logits[(size_t)r1 * NCLS + c], f1[c]);
                }
            }
        }
    }
}

// ---------------------------------------------------------------------------
// Weight transpose + bf16 split: W[K,N] -> packed hi/lo [N, K/2]
// ---------------------------------------------------------------------------
__global__ void transpose_split_kernel(const float* __restrict__ W,
                                       uint32_t* __restrict__ oh,
                                       uint32_t* __restrict__ ol, int K, int N)
{
    __shared__ float t[32][33];
    int kb = blockIdx.y * 32, nb = blockIdx.x * 32;
    int tx = threadIdx.x, ty = threadIdx.y;
    t[ty][tx] = W[(size_t)(kb + ty) * N + nb + tx];
    __syncthreads();
    if (tx < 16) {
        int n2 = nb + ty;
        int kp = (kb >> 1) + tx;
        uint32_t h, l;
        split2(make_float2(t[2 * tx][ty], t[2 * tx + 1][ty]), h, l);
        oh[(size_t)n2 * (K >> 1) + kp] = h;
        ol[(size_t)n2 * (K >> 1) + kp] = l;
    }
}

// ---------------------------------------------------------------------------
// CSR build
// ---------------------------------------------------------------------------
__global__ void csr_count_kernel(const int* __restrict__ ei, int E,
                                 int* __restrict__ cnt)
{
    int i = blockIdx.x * blockDim.x + threadIdx.x;
    if (i < E) atomicAdd(&cnt[ei[E + i]], 1);
}

__global__ __launch_bounds__(1024) void csr_scan_kernel(
    const int* __restrict__ cnt, int* __restrict__ offs,
    int* __restrict__ cur, int n)
{
    __shared__ int smbuf[1024];
    __shared__ int carry;
    if (threadIdx.x == 0) { carry = 0; offs[0] = 0; }
    __syncthreads();
    for (int base = 0; base < n; base += 1024) {
        int i = base + threadIdx.x;
        int v = (i < n) ? cnt[i] : 0;
        smbuf[threadIdx.x] = v;
        __syncthreads();
        #pragma unroll
        for (int off = 1; off < 1024; off <<= 1) {
            int t = (threadIdx.x >= off) ? smbuf[threadIdx.x - off] : 0;
            __syncthreads();
            smbuf[threadIdx.x] += t;
            __syncthreads();
        }
        if (i < n) {
            int inc = carry + smbuf[threadIdx.x];
            offs[i + 1] = inc;
            cur[i] = inc - v;
        }
        __syncthreads();
        if (threadIdx.x == 0) carry += smbuf[1023];
        __syncthreads();
    }
}

__global__ void csr_scatter_kernel(const int* __restrict__ ei, int E,
                                   int* __restrict__ cur,
                                   int* __restrict__ csrc)
{
    int i = blockIdx.x * blockDim.x + threadIdx.x;
    if (i >= E) return;
    int d = ei[E + i];
    int p = atomicAdd(&cur[d], 1);
    csrc[p] = ei[i];
}

// ---------------------------------------------------------------------------
// Fused CSR aggregation: attention weights inline, no atomics, fp32 out.
// One warp per destination node; F = 256.
// ---------------------------------------------------------------------------
__global__ void aggregate_csr_kernel(
    const int* __restrict__ offs, const int* __restrict__ csrc,
    const float* __restrict__ asrc, const float* __restrict__ adst,
    const float* __restrict__ hfeat, const float* __restrict__ bias,
    int Nn, int H, int cshift, float* __restrict__ out)
{
    int node = (blockIdx.x * blockDim.x + threadIdx.x) >> 5;
    int lane = threadIdx.x & 31;
    if (node >= Nn) return;
    const int hsel = (H > 1) ? (lane >> (cshift - 3)) : 0;

    const float adn = adst[node * H + hsel];

    float v = asrc[node * H + hsel] + adn;
    float w = expf((v > 0.f) ? v : SLOPE * v);
    float wsum = w;
    const float4* hp = (const float4*)(hfeat + (size_t)node * 256 + lane * 8);
    float4 u = hp[0], vv4 = hp[1];
    float a0 = w * u.x,   a1 = w * u.y,   a2 = w * u.z,   a3 = w * u.w;
    float a4 = w * vv4.x, a5 = w * vv4.y, a6 = w * vv4.z, a7 = w * vv4.w;

    const int e1 = offs[node + 1];
    for (int e = offs[node]; e < e1; e++) {
        int s = csrc[e];
        if (s != node) {
            float ve = asrc[s * H + hsel] + adn;
            float we = expf((ve > 0.f) ? ve : SLOPE * ve);
            wsum += we;
            const float4* sp = (const float4*)(hfeat + (size_t)s * 256 + lane * 8);
            float4 p = sp[0], q = sp[1];
            a0 = fmaf(we, p.x, a0); a1 = fmaf(we, p.y, a1);
            a2 = fmaf(we, p.z, a2); a3 = fmaf(we, p.w, a3);
            a4 = fmaf(we, q.x, a4); a5 = fmaf(we, q.y, a5);
            a6 = fmaf(we, q.z, a6); a7 = fmaf(we, q.w, a7);
        }
    }

    const float inv = 1.0f / wsum;
    const int colb = lane * 8;
    float4 o0, o1v;
    o0.x  = fmaxf(fmaf(a0, inv, bias[colb + 0]), 0.f);
    o0.y  = fmaxf(fmaf(a1, inv, bias[colb + 1]), 0.f);
    o0.z  = fmaxf(fmaf(a2, inv, bias[colb + 2]), 0.f);
    o0.w  = fmaxf(fmaf(a3, inv, bias[colb + 3]), 0.f);
    o1v.x = fmaxf(fmaf(a4, inv, bias[colb + 4]), 0.f);
    o1v.y = fmaxf(fmaf(a5, inv, bias[colb + 5]), 0.f);
    o1v.z = fmaxf(fmaf(a6, inv, bias[colb + 6]), 0.f);
    o1v.w = fmaxf(fmaf(a7, inv, bias[colb + 7]), 0.f);
    float4* op = (float4*)(out + (size_t)node * 256 + colb);
    op[0] = o0;
    op[1] = o1v;
}

// ---------------------------------------------------------------------------
// Softmax over accumulated logits: out[n] = softmax(relu(logits[n] + b))
// ---------------------------------------------------------------------------
__global__ void softmax_kernel(float* __restrict__ out,
                               const float* __restrict__ b, int Nn)
{
    int n = blockIdx.x * blockDim.x + threadIdx.x;
    if (n >= Nn) return;
    float v[NCLS];
    float m = -1e30f;
    #pragma unroll
    for (int c = 0; c < NCLS; c++) {
        float t = fmaxf(out[(size_t)n * NCLS + c] + b[c], 0.f);
        v[c] = t;
        m = fmaxf(m, t);
    }
    float s = 0.f;
    #pragma unroll
    for (int c = 0; c < NCLS; c++) { v[c] = expf(v[c] - m); s += v[c]; }
    float inv = 1.f / s;
    #pragma unroll
    for (int c = 0; c < NCLS; c++) out[(size_t)n * NCLS + c] = v[c] * inv;
}

// ---------------------------------------------------------------------------
// Launch
// ---------------------------------------------------------------------------
static inline int ceil_div(int a, int b) { return (a + b - 1) / b; }

extern "C" void kernel_launch(void* const* d_in, const int* in_sizes, int n_in,
                              void* d_out, int out_size)
{
    const float* x      = (const float*)d_in[0];
    const int*   ei     = (const int*)  d_in[1];
    const float* W0     = (const float*)d_in[2];
    const float* a_src0 = (const float*)d_in[3];
    const float* a_dst0 = (const float*)d_in[4];
    const float* b0     = (const float*)d_in[5];
    const float* W1     = (const float*)d_in[6];
    const float* a_src1 = (const float*)d_in[7];
    const float* a_dst1 = (const float*)d_in[8];
    const float* b1     = (const float*)d_in[9];
    const float* lw1    = (const float*)d_in[10];
    const float* lb1    = (const float*)d_in[11];
    const float* lw2    = (const float*)d_in[12];
    const float* lb2    = (const float*)d_in[13];
    const float* lw3    = (const float*)d_in[14];
    const float* lb3    = (const float*)d_in[15];
    float* out = (float*)d_out;

    const int Nn = in_sizes[0] / F_IN;
    const int E  = in_sizes[1] / 2;

    float *p_h, *p_out, *p_out2, *p_t1, *p_asrc, *p_adst;
    uint32_t *p_w0h, *p_w0l, *p_w1h, *p_w1l, *p_w2h, *p_w2l, *p_w3h, *p_w3l;
    int *p_cnt, *p_offs, *p_cur, *p_csrc;
    cudaGetSymbolAddress((void**)&p_h,    g_h);
    cudaGetSymbolAddress((void**)&p_out,  g_out);
    cudaGetSymbolAddress((void**)&p_out2, g_out2);
    cudaGetSymbolAddress((void**)&p_t1,   g_t1);
    cudaGetSymbolAddress((void**)&p_asrc, g_asrc);
    cudaGetSymbolAddress((void**)&p_adst, g_adst);
    cudaGetSymbolAddress((void**)&p_w0h, g_w0h);  cudaGetSymbolAddress((void**)&p_w0l, g_w0l);
    cudaGetSymbolAddress((void**)&p_w1h, g_w1h);  cudaGetSymbolAddress((void**)&p_w1l, g_w1l);
    cudaGetSymbolAddress((void**)&p_w2h, g_w2h);  cudaGetSymbolAddress((void**)&p_w2l, g_w2l);
    cudaGetSymbolAddress((void**)&p_w3h, g_w3h);  cudaGetSymbolAddress((void**)&p_w3l, g_w3l);
    cudaGetSymbolAddress((void**)&p_cnt,  g_cnt);
    cudaGetSymbolAddress((void**)&p_offs, g_offs);
    cudaGetSymbolAddress((void**)&p_cur,  g_cur);
    cudaGetSymbolAddress((void**)&p_csrc, g_csrc);

    cudaFuncSetAttribute(mma_gemm, cudaFuncAttributeMaxDynamicSharedMemorySize,
                         GEMM_SMEM_BYTES);

    const int gy = ceil_div(Nn, 128);
    dim3 tb(32, 32);

    // zero alpha accumulators (layer 0) and output logits
    cudaMemsetAsync(p_asrc, 0, (size_t)Nn * H0 * sizeof(float), 0);
    cudaMemsetAsync(p_adst, 0, (size_t)Nn * H0 * sizeof(float), 0);
    cudaMemsetAsync(out, 0, (size_t)Nn * NCLS * sizeof(float), 0);

    transpose_split_kernel<<<dim3(256 / 32, 128 / 32), tb>>>(W0,  p_w0h, p_w0l, 128, 256);
    transpose_split_kernel<<<dim3(256 / 32, 256 / 32), tb>>>(W1,  p_w1h, p_w1l, 256, 256);
    transpose_split_kernel<<<dim3(512 / 32, 256 / 32), tb>>>(lw1, p_w2h, p_w2l, 256, 512);
    // GEMM1 (h0 = x @ W0, fused alpha for layer 0)
    mma_gemm<<<dim3(F0 / 128, gy), 256, GEMM_SMEM_BYTES>>>(
        Nn, F0, F_IN, x, p_w0h, p_w0l, nullptr, p_h, 0,
        1, a_src0, a_dst0, p_asrc, p_adst, H0, 6,
        0, nullptr, nullptr);

    transpose_split_kernel<<<dim3(1024 / 32, 512 / 32), tb>>>(lw2, p_w3h, p_w3l, 512, 1024);

    // CSR build (reused by both layers)
    cudaMemsetAsync(p_cnt, 0, Nn * sizeof(int), 0);
    csr_count_kernel<<<ceil_div(E, 256), 256>>>(ei, E, p_cnt);
    csr_scan_kernel<<<1, 1024>>>(p_cnt, p_offs, p_cur, Nn);
    csr_scatter_kernel<<<ceil_div(E, 256), 256>>>(ei, E, p_cur, p_csrc);

    // ---------------- GAT layer 0 (GEMM1 + alpha already done) ------------
    aggregate_csr_kernel<<<ceil_div(Nn * 32, 256), 256>>>(
        p_offs, p_csrc, p_asrc, p_adst, p_h, b0, Nn, H0, 6, p_out);

    // ---------------- GAT layer 1 ----------------
    cudaMemsetAsync(p_asrc, 0, (size_t)Nn * H1 * sizeof(float), 0);
    cudaMemsetAsync(p_adst, 0, (size_t)Nn * H1 * sizeof(float), 0);
    mma_gemm<<<dim3(F1 / 128, gy), 256, GEMM_SMEM_BYTES>>>(
        Nn, F1, F0, p_out, p_w1h, p_w1l, nullptr, p_h, 0,
        1, a_src1, a_dst1, p_asrc, p_adst, H1, 8,
        0, nullptr, nullptr);
    aggregate_csr_kernel<<<ceil_div(Nn * 32, 256), 256>>>(
        p_offs, p_csrc, p_asrc, p_adst, p_h, b1, Nn, H1, 8, p_out2);

    // ---------------- MLP ----------------
    mma_gemm<<<dim3(512 / 128, gy), 256, GEMM_SMEM_BYTES>>>(
        Nn, 512, 256, p_out2, p_w2h, p_w2l, lb1, p_t1, 1,
        0, nullptr, nullptr, nullptr, nullptr, 1, 8,
        0, nullptr, nullptr);
    // GEMM4: no fp32 C write; fused final layer accumulates logits into out.
    mma_gemm<<<dim3(1024 / 128, gy), 256, GEMM_SMEM_BYTES>>>(
        Nn, 1024, 512, p_t1, p_w3h, p_w3l, lb2, nullptr, 1,
        0, nullptr, nullptr, nullptr, nullptr, 1, 8,
        1, lw3, out);
    softmax_kernel<<<ceil_div(Nn, 256), 256>>>(out, lb3, Nn);
}